// round 1
// baseline (speedup 1.0000x reference)
#include <cuda_runtime.h>

#define NQ 4
#define NL 8
#define NGATES ((NL + 1) * NQ)      // 36 shared gates
#define U_FLOATS (NGATES * 8)       // 288 floats
#define NLAMBDA (NL * NQ)           // 32

// Precomputed shared gate matrices U = RZ(t2)*RY(t1)*RX(t0), one per (layer,qubit).
// Layout per gate: u00r,u00i,u01r,u01i,u10r,u10i,u11r,u11i
__device__ float g_U[U_FLOATS];

__global__ void prep_kernel(const float* __restrict__ theta) {
    int g = threadIdx.x;
    if (g >= NGATES) return;
    float t0 = theta[g * 3 + 0], t1 = theta[g * 3 + 1], t2 = theta[g * 3 + 2];
    float cx, sx, cy, sy, cz, sz;
    sincosf(0.5f * t0, &sx, &cx);
    sincosf(0.5f * t1, &sy, &cy);
    sincosf(0.5f * t2, &sz, &cz);
    // M = RY*RX:
    // m00 = cy*cx + i*sy*sx ; m01 = -sy*cx - i*cy*sx
    // m10 = sy*cx - i*cy*sx ; m11 =  cy*cx - i*sy*sx
    float m00r = cy * cx, m00i = sy * sx;
    float m01r = -sy * cx, m01i = -cy * sx;
    float m10r = sy * cx, m10i = -cy * sx;
    float m11r = cy * cx, m11i = -sy * sx;
    // U = RZ * M: row0 *= (cz - i sz); row1 *= (cz + i sz)
    float* u = &g_U[g * 8];
    u[0] = cz * m00r + sz * m00i;  u[1] = cz * m00i - sz * m00r;
    u[2] = cz * m01r + sz * m01i;  u[3] = cz * m01i - sz * m01r;
    u[4] = cz * m10r - sz * m10i;  u[5] = cz * m10i + sz * m10r;
    u[6] = cz * m11r - sz * m11i;  u[7] = cz * m11i + sz * m11r;
}

__device__ __forceinline__ float2 cmul(float2 a, float2 b) {
    return make_float2(a.x * b.x - a.y * b.y, a.x * b.y + a.y * b.x);
}

// General 2x2 complex gate on qubit with amplitude stride k (k = 8 >> q).
__device__ __forceinline__ void apply_u(float2 s[16], float4 u0, float4 u1, int k) {
#pragma unroll
    for (int i = 0; i < 16; i++) {
        if (i & k) continue;
        float2 a = s[i], b = s[i | k];
        s[i].x     = u0.x * a.x - u0.y * a.y + u0.z * b.x - u0.w * b.y;
        s[i].y     = u0.x * a.y + u0.y * a.x + u0.z * b.y + u0.w * b.x;
        s[i | k].x = u1.x * a.x - u1.y * a.y + u1.z * b.x - u1.w * b.y;
        s[i | k].y = u1.x * a.y + u1.y * a.x + u1.z * b.y + u1.w * b.x;
    }
}

// RX gate: [[c, -i s],[-i s, c]] — real-structured, 8 FMA per amplitude pair.
__device__ __forceinline__ void apply_rx(float2 s[16], float c, float sn, int k) {
#pragma unroll
    for (int i = 0; i < 16; i++) {
        if (i & k) continue;
        float2 a = s[i], b = s[i | k];
        s[i].x     = c * a.x + sn * b.y;
        s[i].y     = c * a.y - sn * b.x;
        s[i | k].x = c * b.x + sn * a.y;
        s[i | k].y = c * b.y - sn * a.x;
    }
}

__global__ void __launch_bounds__(256)
pqc_kernel(const float* __restrict__ x, const float* __restrict__ lmbd,
           float* __restrict__ out, int B) {
    __shared__ float sU[U_FLOATS];
    __shared__ float sl[NLAMBDA];
    int t = threadIdx.x;
    for (int i = t; i < U_FLOATS; i += blockDim.x) sU[i] = g_U[i];
    if (t < NLAMBDA) sl[t] = lmbd[t];
    __syncthreads();

    int b = blockIdx.x * blockDim.x + t;
    if (b >= B) return;

    float4 xv = reinterpret_cast<const float4*>(x)[b];
    float xa[4] = {xv.x, xv.y, xv.z, xv.w};

    // Init: layer-0 shared gates applied to |0000> = outer product of column-0 of U_{0,q}.
    // Amplitude index i = b0*8 + b1*4 + b2*2 + b3 (qubit q -> bit (3-q)).
    float2 s[16];
    {
        float2 c0[2], c1[2], c2[2], c3[2];
        c0[0] = make_float2(sU[0], sU[1]);   c0[1] = make_float2(sU[4], sU[5]);
        c1[0] = make_float2(sU[8], sU[9]);   c1[1] = make_float2(sU[12], sU[13]);
        c2[0] = make_float2(sU[16], sU[17]); c2[1] = make_float2(sU[20], sU[21]);
        c3[0] = make_float2(sU[24], sU[25]); c3[1] = make_float2(sU[28], sU[29]);
#pragma unroll
        for (int i = 0; i < 16; i++) {
            float2 a = cmul(c0[(i >> 3) & 1], c1[(i >> 2) & 1]);
            a = cmul(a, c2[(i >> 1) & 1]);
            s[i] = cmul(a, c3[i & 1]);
        }
    }

    // CZ ring sign mask: negate amplitudes where parity of (b0b1+b1b2+b2b3+b3b0) is odd
    // -> indices 3, 6, 9, 12.
#pragma unroll 1
    for (int l = 0; l < NL; l++) {
        // CZ layer
        s[3].x = -s[3].x;   s[3].y = -s[3].y;
        s[6].x = -s[6].x;   s[6].y = -s[6].y;
        s[9].x = -s[9].x;   s[9].y = -s[9].y;
        s[12].x = -s[12].x; s[12].y = -s[12].y;

        // per-sample RX encoding gates
#pragma unroll
        for (int q = 0; q < 4; q++) {
            float ang = 0.5f * sl[l * 4 + q] * xa[q];
            float sn, cn;
            __sincosf(ang, &sn, &cn);
            apply_rx(s, cn, sn, 8 >> q);
        }

        // shared variational gates of next layer (layer l+1; l=7 -> final layer 8)
#pragma unroll
        for (int q = 0; q < 4; q++) {
            const float4* u4 = reinterpret_cast<const float4*>(&sU[((l + 1) * 4 + q) * 8]);
            float4 ua = u4[0], ub = u4[1];
            apply_u(s, ua, ub, 8 >> q);
        }
    }

    // <Z0 Z1 Z2 Z3>: parity mask 0x6996 marks odd-popcount indices (weight -1).
    float e = 0.0f;
#pragma unroll
    for (int i = 0; i < 16; i++) {
        float p = s[i].x * s[i].x + s[i].y * s[i].y;
        e += ((0x6996 >> i) & 1) ? -p : p;
    }
    out[b] = e;
}

extern "C" void kernel_launch(void* const* d_in, const int* in_sizes, int n_in,
                              void* d_out, int out_size) {
    const float* x     = (const float*)d_in[0];   // [B, 4]
    const float* theta = (const float*)d_in[1];   // [1, 108]
    const float* lmbd  = (const float*)d_in[2];   // [32]
    float* out = (float*)d_out;                   // [B, 1]
    int B = in_sizes[0] / NQ;

    prep_kernel<<<1, 64>>>(theta);
    int threads = 256;
    int blocks = (B + threads - 1) / threads;
    pqc_kernel<<<blocks, threads>>>(x, lmbd, out, B);
}

// round 2
// speedup vs baseline: 1.1382x; 1.1382x over previous
#include <cuda_runtime.h>

#define NQ 4
#define NL 8

typedef unsigned long long u64;

// ---------- packed f32x2 helpers ----------
__device__ __forceinline__ u64 pk2(float lo, float hi) {
    u64 r; asm("mov.b64 %0, {%1,%2};" : "=l"(r) : "f"(lo), "f"(hi)); return r;
}
__device__ __forceinline__ u64 bc2(float v) { return pk2(v, v); }
__device__ __forceinline__ u64 fma2(u64 a, u64 b, u64 c) {
    u64 d; asm("fma.rn.f32x2 %0, %1, %2, %3;" : "=l"(d) : "l"(a), "l"(b), "l"(c)); return d;
}
__device__ __forceinline__ u64 mul2(u64 a, u64 b) {
    u64 d; asm("mul.rn.f32x2 %0, %1, %2;" : "=l"(d) : "l"(a), "l"(b)); return d;
}
__device__ __forceinline__ u64 swp2(u64 v) {
    float a, b; asm("mov.b64 {%0,%1}, %2;" : "=f"(a), "=f"(b) : "l"(v)); return pk2(b, a);
}
__device__ __forceinline__ void unpk2(u64 v, float& a, float& b) {
    asm("mov.b64 {%0,%1}, %2;" : "=f"(a), "=f"(b) : "l"(v));
}

__device__ __forceinline__ float2 cmulf(float2 a, float2 b) {
    return make_float2(a.x * b.x - a.y * b.y, a.x * b.y + a.y * b.x);
}

// General 2x2 complex gate on qubit q<3 (m-space stride km = 4>>q).
// p: 12 broadcast packs in shared:
//  0:u00r 1:u00i 2:-u00i 3:u01r 4:u01i 5:-u01i 6:u10r 7:u10i 8:-u10i 9:u11r 10:u11i 11:-u11i
__device__ __forceinline__ void apply_u_k(u64 VR[8], u64 VI[8], const u64* __restrict__ p, int km) {
    u64 p0 = p[0], p1 = p[1], p2 = p[2], p3 = p[3], p4 = p[4], p5 = p[5];
    u64 p6 = p[6], p7 = p[7], p8 = p[8], p9 = p[9], p10 = p[10], p11 = p[11];
#pragma unroll
    for (int mm = 0; mm < 4; mm++) {
        int m = ((mm & ~(km - 1)) << 1) | (mm & (km - 1));
        int n = m | km;
        u64 ar = VR[m], ai = VI[m], br = VR[n], bi = VI[n];
        VR[m] = fma2(p5, bi, fma2(p3, br, fma2(p2, ai, mul2(p0, ar))));
        VI[m] = fma2(p4, br, fma2(p3, bi, fma2(p1, ar, mul2(p0, ai))));
        VR[n] = fma2(p11, bi, fma2(p9, br, fma2(p8, ai, mul2(p6, ar))));
        VI[n] = fma2(p10, br, fma2(p9, bi, fma2(p7, ar, mul2(p6, ai))));
    }
}

// General 2x2 complex gate on qubit 3 (lane qubit).
// p: 6 lane-swizzled packs: 0:A={u00r,u11r} 1:B={u01r,u10r} 2:C={u00i,u11i} 3:D={u01i,u10i} 4:-C 5:-D
__device__ __forceinline__ void apply_u_lane(u64 VR[8], u64 VI[8], const u64* __restrict__ p) {
    u64 A = p[0], B = p[1], C = p[2], D = p[3], nC = p[4], nD = p[5];
#pragma unroll
    for (int m = 0; m < 8; m++) {
        u64 r = VR[m], i = VI[m];
        u64 rs = swp2(r), is = swp2(i);
        VR[m] = fma2(nD, is, fma2(nC, i, fma2(B, rs, mul2(A, r))));
        VI[m] = fma2(D, rs, fma2(C, r, fma2(B, is, mul2(A, i))));
    }
}

// RX on qubit q<3: coefficients broadcast cp={c,c}, sp={s,s}, np={-s,-s}
__device__ __forceinline__ void apply_rx_k(u64 VR[8], u64 VI[8], u64 cp, u64 sp, u64 np, int km) {
#pragma unroll
    for (int mm = 0; mm < 4; mm++) {
        int m = ((mm & ~(km - 1)) << 1) | (mm & (km - 1));
        int n = m | km;
        u64 ar = VR[m], ai = VI[m], br = VR[n], bi = VI[n];
        VR[m] = fma2(sp, bi, mul2(cp, ar));
        VI[m] = fma2(np, br, mul2(cp, ai));
        VR[n] = fma2(sp, ai, mul2(cp, br));
        VI[n] = fma2(np, ar, mul2(cp, bi));
    }
}

// RX on qubit 3 (lane qubit)
__device__ __forceinline__ void apply_rx_lane(u64 VR[8], u64 VI[8], u64 cp, u64 sp, u64 np) {
#pragma unroll
    for (int m = 0; m < 8; m++) {
        u64 r = VR[m], i = VI[m];
        u64 rs = swp2(r), is = swp2(i);
        VR[m] = fma2(sp, is, mul2(cp, r));
        VI[m] = fma2(np, rs, mul2(cp, i));
    }
}

__global__ void __launch_bounds__(256)
pqc_kernel(const float* __restrict__ x, const float* __restrict__ theta,
           const float* __restrict__ lmbd, float* __restrict__ out, int B) {
    // sG: per layer (1..8) 42 packs: q=0,1,2 -> 12 packs each at q*12; q=3 -> 6 packs at 36
    __shared__ u64 sG[8 * 42];
    __shared__ float sInit[16];   // layer-0 gates, column 0: per qubit {u00r,u00i,u10r,u10i}
    __shared__ float sl[32];

    int t = threadIdx.x;
    if (t < 32) sl[t] = lmbd[t];

    // ---- in-block prep: 36 threads build gate packs ----
    if (t < 36) {
        int g = t;
        float t0 = theta[g * 3 + 0], t1 = theta[g * 3 + 1], t2 = theta[g * 3 + 2];
        float cx, sx, cy, sy, cz, sz;
        sincosf(0.5f * t0, &sx, &cx);
        sincosf(0.5f * t1, &sy, &cy);
        sincosf(0.5f * t2, &sz, &cz);
        // M = RY*RX
        float m00r = cy * cx, m00i = sy * sx;
        float m01r = -sy * cx, m01i = -cy * sx;
        float m10r = sy * cx, m10i = -cy * sx;
        float m11r = cy * cx, m11i = -sy * sx;
        // U = RZ * M
        float u00r = cz * m00r + sz * m00i, u00i = cz * m00i - sz * m00r;
        float u01r = cz * m01r + sz * m01i, u01i = cz * m01i - sz * m01r;
        float u10r = cz * m10r - sz * m10i, u10i = cz * m10i + sz * m10r;
        float u11r = cz * m11r - sz * m11i, u11i = cz * m11i + sz * m11r;

        int l = g >> 2, q = g & 3;
        if (l == 0) {
            float* si = &sInit[q * 4];
            si[0] = u00r; si[1] = u00i; si[2] = u10r; si[3] = u10i;
        } else {
            u64* pg = &sG[(l - 1) * 42];
            if (q < 3) {
                u64* p = &pg[q * 12];
                p[0] = bc2(u00r);  p[1] = bc2(u00i);  p[2] = bc2(-u00i);
                p[3] = bc2(u01r);  p[4] = bc2(u01i);  p[5] = bc2(-u01i);
                p[6] = bc2(u10r);  p[7] = bc2(u10i);  p[8] = bc2(-u10i);
                p[9] = bc2(u11r);  p[10] = bc2(u11i); p[11] = bc2(-u11i);
            } else {
                u64* p = &pg[36];
                p[0] = pk2(u00r, u11r);   // A
                p[1] = pk2(u01r, u10r);   // B
                p[2] = pk2(u00i, u11i);   // C
                p[3] = pk2(u01i, u10i);   // D
                p[4] = pk2(-u00i, -u11i); // -C
                p[5] = pk2(-u01i, -u10i); // -D
            }
        }
    }
    __syncthreads();

    int b = blockIdx.x * blockDim.x + t;
    if (b >= B) return;

    float4 xv = reinterpret_cast<const float4*>(x)[b];
    float xa[4] = {xv.x, xv.y, xv.z, xv.w};

    // ---- init: layer-0 applied to |0000> = outer product of column-0 entries ----
    // amplitude index i: qubit q -> bit (3-q); lane = bit0 (qubit 3); m = i>>1
    u64 VR[8], VI[8];
    {
        float2 c0[2] = {{sInit[0], sInit[1]}, {sInit[2], sInit[3]}};
        float2 c1[2] = {{sInit[4], sInit[5]}, {sInit[6], sInit[7]}};
        float2 c2[2] = {{sInit[8], sInit[9]}, {sInit[10], sInit[11]}};
        float2 c3[2] = {{sInit[12], sInit[13]}, {sInit[14], sInit[15]}};
        float2 t01[4], t23[4];
#pragma unroll
        for (int j = 0; j < 4; j++) {
            t01[j] = cmulf(c0[j >> 1], c1[j & 1]);
            t23[j] = cmulf(c2[j >> 1], c3[j & 1]);
        }
        u64 T23r[2], T23i[2];
#pragma unroll
        for (int b2 = 0; b2 < 2; b2++) {
            T23r[b2] = pk2(t23[b2 * 2 + 0].x, t23[b2 * 2 + 1].x);
            T23i[b2] = pk2(t23[b2 * 2 + 0].y, t23[b2 * 2 + 1].y);
        }
#pragma unroll
        for (int m = 0; m < 8; m++) {
            float2 tt = t01[m >> 1];
            int b2 = m & 1;
            u64 tr = bc2(tt.x), ti = bc2(tt.y), nti = bc2(-tt.y);
            VR[m] = fma2(nti, T23i[b2], mul2(tr, T23r[b2]));
            VI[m] = fma2(ti, T23r[b2], mul2(tr, T23i[b2]));
        }
    }

    const u64 HI_SIGN = 0x8000000000000000ULL;
    const u64 LO_SIGN = 0x0000000080000000ULL;

#pragma unroll 1
    for (int l = 0; l < NL; l++) {
        // CZ ring: negate amplitudes 3 (m1 hi), 6 (m3 lo), 9 (m4 hi), 12 (m6 lo)
        VR[1] ^= HI_SIGN; VI[1] ^= HI_SIGN;
        VR[3] ^= LO_SIGN; VI[3] ^= LO_SIGN;
        VR[4] ^= HI_SIGN; VI[4] ^= HI_SIGN;
        VR[6] ^= LO_SIGN; VI[6] ^= LO_SIGN;

        // per-sample RX encoding gates
#pragma unroll
        for (int q = 0; q < 4; q++) {
            float ang = 0.5f * sl[l * 4 + q] * xa[q];
            float sn, cn;
            __sincosf(ang, &sn, &cn);
            u64 cp = bc2(cn), sp = bc2(sn), np = bc2(-sn);
            if (q == 0)      apply_rx_k(VR, VI, cp, sp, np, 4);
            else if (q == 1) apply_rx_k(VR, VI, cp, sp, np, 2);
            else if (q == 2) apply_rx_k(VR, VI, cp, sp, np, 1);
            else             apply_rx_lane(VR, VI, cp, sp, np);
        }

        // shared variational gates of layer l+1
        const u64* pg = &sG[l * 42];
        apply_u_k(VR, VI, pg + 0, 4);
        apply_u_k(VR, VI, pg + 12, 2);
        apply_u_k(VR, VI, pg + 24, 1);
        apply_u_lane(VR, VI, pg + 36);
    }

    // <Z0 Z1 Z2 Z3>: i=2m+lane; sign(i) = (-1)^popc(i); lanes of a pair have opposite signs.
    float e = 0.0f;
#pragma unroll
    for (int m = 0; m < 8; m++) {
        u64 p = fma2(VI[m], VI[m], mul2(VR[m], VR[m]));
        float plo, phi;
        unpk2(p, plo, phi);
        float d = plo - phi;
        e += (__popc(m) & 1) ? -d : d;
    }
    out[b] = e;
}

extern "C" void kernel_launch(void* const* d_in, const int* in_sizes, int n_in,
                              void* d_out, int out_size) {
    const float* x     = (const float*)d_in[0];   // [B, 4]
    const float* theta = (const float*)d_in[1];   // [1, 108]
    const float* lmbd  = (const float*)d_in[2];   // [32]
    float* out = (float*)d_out;                   // [B, 1]
    int B = in_sizes[0] / NQ;

    int threads = 256;
    int blocks = (B + threads - 1) / threads;
    pqc_kernel<<<blocks, threads>>>(x, theta, lmbd, out, B);
}

// round 5
// speedup vs baseline: 1.5017x; 1.3194x over previous
#include <cuda_runtime.h>

#define NQ 4
#define NL 8

typedef unsigned long long u64;

// ---------- packed f32x2 helpers ----------
__device__ __forceinline__ u64 pk2(float lo, float hi) {
    u64 r; asm("mov.b64 %0, {%1,%2};" : "=l"(r) : "f"(lo), "f"(hi)); return r;
}
__device__ __forceinline__ u64 bc2(float v) { return pk2(v, v); }
__device__ __forceinline__ u64 fma2(u64 a, u64 b, u64 c) {
    u64 d; asm("fma.rn.f32x2 %0, %1, %2, %3;" : "=l"(d) : "l"(a), "l"(b), "l"(c)); return d;
}
__device__ __forceinline__ u64 mul2(u64 a, u64 b) {
    u64 d; asm("mul.rn.f32x2 %0, %1, %2;" : "=l"(d) : "l"(a), "l"(b)); return d;
}
__device__ __forceinline__ u64 swp2(u64 v) {
    float a, b; asm("mov.b64 {%0,%1}, %2;" : "=f"(a), "=f"(b) : "l"(v)); return pk2(b, a);
}
__device__ __forceinline__ void unpk2(u64 v, float& a, float& b) {
    asm("mov.b64 {%0,%1}, %2;" : "=f"(a), "=f"(b) : "l"(v));
}
__device__ __forceinline__ float2 cmulf(float2 a, float2 b) {
    return make_float2(a.x * b.x - a.y * b.y, a.x * b.y + a.y * b.x);
}

// Fused SU(2) gate on qubit q<3 (m-space stride km = 4>>q).
// Gate G = [[g00, -conj(g10)],[g10, conj(g00)]]; 7 broadcast packs.
__device__ __forceinline__ void apply_g_k(u64 VR[8], u64 VI[8],
                                          u64 P00r, u64 P00i, u64 N00i,
                                          u64 P10r, u64 N10r, u64 P10i, u64 N10i,
                                          int km) {
#pragma unroll
    for (int mm = 0; mm < 4; mm++) {
        int m = ((mm & ~(km - 1)) << 1) | (mm & (km - 1));
        int n = m | km;
        u64 ar = VR[m], ai = VI[m], br = VR[n], bi = VI[n];
        VR[m] = fma2(N10i, bi, fma2(N10r, br, fma2(N00i, ai, mul2(P00r, ar))));
        VI[m] = fma2(P10i, br, fma2(N10r, bi, fma2(P00i, ar, mul2(P00r, ai))));
        VR[n] = fma2(P00i, bi, fma2(P00r, br, fma2(N10i, ai, mul2(P10r, ar))));
        VI[n] = fma2(N00i, br, fma2(P00r, bi, fma2(P10i, ar, mul2(P10r, ai))));
    }
}

// Fused SU(2) gate on qubit 3 (lane qubit). Lane-swizzled packs:
// A={g00r,g00r} B={-g10r,g10r} C={g00i,-g00i} D={g10i,g10i} nC=-C nD=-D
__device__ __forceinline__ void apply_g_lane(u64 VR[8], u64 VI[8],
                                             u64 A, u64 B, u64 C, u64 D, u64 nC, u64 nD) {
#pragma unroll
    for (int m = 0; m < 8; m++) {
        u64 r = VR[m], i = VI[m];
        u64 rs = swp2(r), is = swp2(i);
        VR[m] = fma2(nD, is, fma2(nC, i, fma2(B, rs, mul2(A, r))));
        VI[m] = fma2(D, rs, fma2(C, r, fma2(B, is, mul2(A, i))));
    }
}

__global__ void __launch_bounds__(128)
pqc_kernel(const float* __restrict__ x, const float* __restrict__ theta,
           const float* __restrict__ lmbd, float* __restrict__ out, int B) {
    // 36 gates, SU(2): store only {u00r, u00i, u10r, u10i} per gate.
    __shared__ float4 sU4[36];
    __shared__ float sl[32];

    int t = threadIdx.x;
    if (t < 32) sl[t] = lmbd[t];

    if (t < 36) {
        int g = t;
        float t0 = theta[g * 3 + 0], t1 = theta[g * 3 + 1], t2 = theta[g * 3 + 2];
        float cx, sx, cy, sy, cz, sz;
        sincosf(0.5f * t0, &sx, &cx);
        sincosf(0.5f * t1, &sy, &cy);
        sincosf(0.5f * t2, &sz, &cz);
        // M = RY*RX (column 0 entries and row structure)
        float m00r = cy * cx, m00i = sy * sx;
        float m10r = sy * cx, m10i = -cy * sx;
        // U = RZ*M: u00 = (cz - i sz)*m00 ; u10 = (cz + i sz)*m10
        float u00r = cz * m00r + sz * m00i, u00i = cz * m00i - sz * m00r;
        float u10r = cz * m10r - sz * m10i, u10i = cz * m10i + sz * m10r;
        sU4[g] = make_float4(u00r, u00i, u10r, u10i);
    }
    __syncthreads();

    int b = blockIdx.x * blockDim.x + t;
    if (b >= B) return;

    float4 xv = reinterpret_cast<const float4*>(x)[b];
    float xa[4] = {xv.x, xv.y, xv.z, xv.w};

    // ---- init: layer-0 gates on |0000> = outer product of columns-0 (u00, u10) ----
    // amplitude index i: qubit q -> bit (3-q); lane = bit0 (qubit 3); m = i>>1
    u64 VR[8], VI[8];
    {
        float4 g0 = sU4[0], g1 = sU4[1], g2 = sU4[2], g3 = sU4[3];
        float2 c0[2] = {{g0.x, g0.y}, {g0.z, g0.w}};
        float2 c1[2] = {{g1.x, g1.y}, {g1.z, g1.w}};
        float2 c2[2] = {{g2.x, g2.y}, {g2.z, g2.w}};
        float2 c3[2] = {{g3.x, g3.y}, {g3.z, g3.w}};
        float2 t01[4], t23[4];
#pragma unroll
        for (int j = 0; j < 4; j++) {
            t01[j] = cmulf(c0[j >> 1], c1[j & 1]);
            t23[j] = cmulf(c2[j >> 1], c3[j & 1]);
        }
        u64 T23r[2], T23i[2];
#pragma unroll
        for (int b2 = 0; b2 < 2; b2++) {
            T23r[b2] = pk2(t23[b2 * 2 + 0].x, t23[b2 * 2 + 1].x);
            T23i[b2] = pk2(t23[b2 * 2 + 0].y, t23[b2 * 2 + 1].y);
        }
#pragma unroll
        for (int m = 0; m < 8; m++) {
            float2 tt = t01[m >> 1];
            int b2 = m & 1;
            u64 tr = bc2(tt.x), ti = bc2(tt.y), nti = bc2(-tt.y);
            VR[m] = fma2(nti, T23i[b2], mul2(tr, T23r[b2]));
            VI[m] = fma2(ti, T23r[b2], mul2(tr, T23i[b2]));
        }
    }

    const u64 HI_SIGN = 0x8000000000000000ULL;
    const u64 LO_SIGN = 0x0000000080000000ULL;

#pragma unroll 1
    for (int l = 0; l < NL; l++) {
        // CZ ring: negate amplitudes 3 (m1 hi), 6 (m3 lo), 9 (m4 hi), 12 (m6 lo)
        VR[1] ^= HI_SIGN; VI[1] ^= HI_SIGN;
        VR[3] ^= LO_SIGN; VI[3] ^= LO_SIGN;
        VR[4] ^= HI_SIGN; VI[4] ^= HI_SIGN;
        VR[6] ^= LO_SIGN; VI[6] ^= LO_SIGN;

        // Fused gates G_q = U_{l+1,q} * RX(lmbd*x) per qubit (distinct-qubit factors commute)
#pragma unroll
        for (int q = 0; q < 4; q++) {
            float4 u = sU4[(l + 1) * 4 + q];   // {u00r, u00i, u10r, u10i}
            float ang = 0.5f * sl[l * 4 + q] * xa[q];
            float s, c;
            __sincosf(ang, &s, &c);
            // G = U * RX(c, s): (u01 = -conj(u10), u11 = conj(u00))
            // g00 = u00*c + u01*(-i s) ; g10 = u10*c + u11*(-i s)
            float g00r = u.x * c + u.w * s;    // u00r*c + u10i*s
            float g00i = u.y * c + u.z * s;    // u00i*c + u10r*s
            float g10r = u.z * c - u.y * s;    // u10r*c - u00i*s
            float g10i = u.w * c - u.x * s;    // u10i*c - u00r*s
            if (q < 3) {
                u64 P00r = bc2(g00r), P00i = bc2(g00i), N00i = bc2(-g00i);
                u64 P10r = bc2(g10r), N10r = bc2(-g10r);
                u64 P10i = bc2(g10i), N10i = bc2(-g10i);
                apply_g_k(VR, VI, P00r, P00i, N00i, P10r, N10r, P10i, N10i, 4 >> q);
            } else {
                u64 A = bc2(g00r);
                u64 B = pk2(-g10r, g10r);
                u64 C = pk2(g00i, -g00i);
                u64 D = bc2(g10i);
                u64 nC = pk2(-g00i, g00i);
                u64 nD = bc2(-g10i);
                apply_g_lane(VR, VI, A, B, C, D, nC, nD);
            }
        }
    }

    // <Z0 Z1 Z2 Z3>: i=2m+lane; sign = (-1)^popc(i); lanes of a pair have opposite signs.
    float e = 0.0f;
#pragma unroll
    for (int m = 0; m < 8; m++) {
        u64 p = fma2(VI[m], VI[m], mul2(VR[m], VR[m]));
        float plo, phi;
        unpk2(p, plo, phi);
        float d = plo - phi;
        e += (__popc(m) & 1) ? -d : d;
    }
    out[b] = e;
}

extern "C" void kernel_launch(void* const* d_in, const int* in_sizes, int n_in,
                              void* d_out, int out_size) {
    const float* x     = (const float*)d_in[0];   // [B, 4]
    const float* theta = (const float*)d_in[1];   // [1, 108]
    const float* lmbd  = (const float*)d_in[2];   // [32]
    float* out = (float*)d_out;                   // [B, 1]
    int B = in_sizes[0] / NQ;

    int threads = 128;
    int blocks = (B + threads - 1) / threads;
    pqc_kernel<<<blocks, threads>>>(x, theta, lmbd, out, B);
}